// round 14
// baseline (speedup 1.0000x reference)
#include <cuda_runtime.h>
#include <cstdint>

#define HH 64
#define WW 64
#define HW 4096
#define CCH 256
#define NK 33

// Scratch
__device__ float g_G[2u * 256u * 4096u];  // G[b][d][p] = Mt @ Fte + u
__device__ float g_M[256u * 256u];        // Mt[d][c]
__device__ float g_u[256u];               // u[d]
__device__ unsigned g_gate = 0u;
__device__ unsigned g_done = 0u;

// ---------------------------------------------------------------------------
// f32x2 packed helpers (FFMA2 via PTX fma.rn.f32x2)
// ---------------------------------------------------------------------------
__device__ __forceinline__ unsigned long long pack2_bcast(float x) {
  unsigned long long r;
  asm("mov.b64 %0, {%1, %1};" : "=l"(r) : "f"(x));
  return r;
}
__device__ __forceinline__ unsigned long long ffma2(unsigned long long a,
                                                    unsigned long long b,
                                                    unsigned long long c) {
  unsigned long long d;
  asm("fma.rn.f32x2 %0, %1, %2, %3;" : "=l"(d) : "l"(a), "l"(b), "l"(c));
  return d;
}
__device__ __forceinline__ void unpack2(unsigned long long v, float& lo, float& hi) {
  asm("mov.b64 {%0, %1}, %2;" : "=f"(lo), "=f"(hi) : "l"(v));
}

// ---------------------------------------------------------------------------
// Kernel 1 (fused): prep (Mt, u) + G = Mt @ Fte + u.  (R8 verbatim — 43 us)
// ---------------------------------------------------------------------------
#define PSTR 36
#define FUSED_SMEM (2 * 256 * PSTR * (int)sizeof(float))  // 73728 B

__global__ __launch_bounds__(256) void psla_gemm_fused(
    const float* __restrict__ Fte, const float* __restrict__ Wf,
    const float* __restrict__ Wg, const float* __restrict__ bg) {
  extern __shared__ float dsm[];
  const int bid = blockIdx.x;
  const int tid = threadIdx.x;

  if (bid < 64) {
    float (*sg)[PSTR] = (float (*)[PSTR])dsm;
    float (*sf)[PSTR] = (float (*)[PSTR])(dsm + 256 * PSTR);
    const int c0 = (bid & 7) * 32;
    const int d0 = (bid >> 3) * 32;

    float4 ga[8], fa[8];
#pragma unroll
    for (int j = 0; j < 8; j++) {
      ga[j] = *(const float4*)(Wg + (size_t)tid * 256 + c0 + 4 * j);
      fa[j] = *(const float4*)(Wf + (size_t)tid * 256 + d0 + 4 * j);
    }
#pragma unroll
    for (int j = 0; j < 8; j++) {
      *(float4*)&sg[tid][4 * j] = ga[j];
      *(float4*)&sf[tid][4 * j] = fa[j];
    }
    __syncthreads();

    const int tc = (tid & 15) * 2, td = (tid >> 4) * 2;
    float a00 = 0.f, a01 = 0.f, a10 = 0.f, a11 = 0.f;
#pragma unroll 8
    for (int kk = 0; kk < 256; kk++) {
      const float2 g2 = *(const float2*)&sg[kk][tc];
      const float2 f2 = *(const float2*)&sf[kk][td];
      a00 = fmaf(f2.x, g2.x, a00);
      a01 = fmaf(f2.x, g2.y, a01);
      a10 = fmaf(f2.y, g2.x, a10);
      a11 = fmaf(f2.y, g2.y, a11);
    }
    g_M[(size_t)(d0 + td + 0) * 256 + c0 + tc + 0] = a00;
    g_M[(size_t)(d0 + td + 0) * 256 + c0 + tc + 1] = a01;
    g_M[(size_t)(d0 + td + 1) * 256 + c0 + tc + 0] = a10;
    g_M[(size_t)(d0 + td + 1) * 256 + c0 + tc + 1] = a11;

    __threadfence();
    __syncthreads();
    if (tid == 0) atomicAdd(&g_gate, 1u);
  } else if (bid == 64) {
    float s0 = 0.f, s1 = 0.f, s2 = 0.f, s3 = 0.f;
#pragma unroll
    for (int o = 0; o < 256; o += 4) {
      s0 = fmaf(bg[o + 0], Wf[(o + 0) * 256 + tid], s0);
      s1 = fmaf(bg[o + 1], Wf[(o + 1) * 256 + tid], s1);
      s2 = fmaf(bg[o + 2], Wf[(o + 2) * 256 + tid], s2);
      s3 = fmaf(bg[o + 3], Wf[(o + 3) * 256 + tid], s3);
    }
    g_u[tid] = (s0 + s1) + (s2 + s3);
    __threadfence();
    __syncthreads();
    if (tid == 0) atomicAdd(&g_gate, 1u);
  }

  if (tid == 0) {
    while (atomicAdd(&g_gate, 0u) < 65u) __nanosleep(64);
  }
  __syncthreads();

  {
    float* sA = dsm;            // [8][132]
    float* sB = dsm + 8 * 132;  // [8][132]

    const int yy = bid >> 5;
    const int b = yy & 1;
    const int o0 = (yy >> 1) * 128;
    const int p0 = (bid & 31) * 128;
    const float* X = Fte + (size_t)b * CCH * HW;
    float* Go = g_G + (size_t)b * CCH * HW;

    const int tx = tid & 15, ty = tid >> 4;

    unsigned long long acc2[8][4];
#pragma unroll
    for (int i = 0; i < 8; i++)
#pragma unroll
      for (int j = 0; j < 4; j++) acc2[i][j] = 0ull;

    const int arow = tid >> 1, acg = (tid & 1) * 4;
    const int brow = tid >> 5, bcol = (tid & 31) * 4;

    for (int k0 = 0; k0 < CCH; k0 += 8) {
      float4 av = *(const float4*)(g_M + (size_t)(o0 + arow) * CCH + k0 + acg);
      float4 bv = *(const float4*)(X + (size_t)(k0 + brow) * HW + p0 + bcol);
      __syncthreads();
      sA[(acg + 0) * 132 + arow] = av.x;
      sA[(acg + 1) * 132 + arow] = av.y;
      sA[(acg + 2) * 132 + arow] = av.z;
      sA[(acg + 3) * 132 + arow] = av.w;
      *(float4*)&sB[brow * 132 + bcol] = bv;
      __syncthreads();
#pragma unroll
      for (int kk = 0; kk < 8; kk++) {
        float a[8];
        *(float4*)&a[0] = *(const float4*)&sA[kk * 132 + ty * 8];
        *(float4*)&a[4] = *(const float4*)&sA[kk * 132 + ty * 8 + 4];
        unsigned long long b2[4];
        ulonglong2 bl0 = *(const ulonglong2*)&sB[kk * 132 + tx * 8];
        ulonglong2 bl1 = *(const ulonglong2*)&sB[kk * 132 + tx * 8 + 4];
        b2[0] = bl0.x; b2[1] = bl0.y; b2[2] = bl1.x; b2[3] = bl1.y;
        unsigned long long a2[8];
#pragma unroll
        for (int i = 0; i < 8; i++) a2[i] = pack2_bcast(a[i]);
#pragma unroll
        for (int i = 0; i < 8; i++)
#pragma unroll
          for (int j = 0; j < 4; j++)
            acc2[i][j] = ffma2(a2[i], b2[j], acc2[i][j]);
      }
    }

#pragma unroll
    for (int i = 0; i < 8; i++) {
      const int o = o0 + ty * 8 + i;
      const float bvv = g_u[o];
      float r[8];
#pragma unroll
      for (int j = 0; j < 4; j++) unpack2(acc2[i][j], r[2 * j], r[2 * j + 1]);
#pragma unroll
      for (int j = 0; j < 8; j += 4) {
        float4 v;
        v.x = r[j + 0] + bvv;
        v.y = r[j + 1] + bvv;
        v.z = r[j + 2] + bvv;
        v.w = r[j + 3] + bvv;
        *(float4*)(Go + (size_t)o * HW + p0 + tx * 8 + j) = v;
      }
    }
  }

  __syncthreads();
  if (tid == 0) {
    const unsigned d = atomicAdd(&g_done, 1u);
    if (d == 127u) {
      atomicExch(&g_gate, 0u);
      atomicExch(&g_done, 0u);
    }
  }
}

// ---------------------------------------------------------------------------
// Kernel 2: sparse local attention, v10 — 2 CTAs/SM, decoupled barriers.
// Tile = 8(x) x 4(y) px. 256 threads = 32 px * 8 subs of 4 ch.
// Halo 16x12 = 192 sites; triple-buffered smem [3][192][36] = 82944 B
// -> 2 CTAs/SM.  Pipeline per chunk: fetch(c+2) -> compute(c) -> store(c+1).
// grid = 8 x 16 x 2 = 256 CTAs = one wave at 2 CTAs/SM.
// ---------------------------------------------------------------------------
#define SST 36
#define NSITE 192
#define ABUF (NSITE * SST)  // 6912 floats per buffer

// Thread (px, sub) loads sites t*32+px (t=0..5), channels sub*4..sub*4+3.
__device__ __forceinline__ void fetch6(const float* __restrict__ P, int base,
                                       int chbase, const bool* hin,
                                       const int* ha, float4* hv) {
#pragma unroll
  for (int t = 0; t < 6; t++) {
    const float* p0 = P + (size_t)(base + chbase) * HW + ha[t];
    float4 v;
    v.x = hin[t] ? p0[0] : 0.f;
    v.y = hin[t] ? p0[HW] : 0.f;
    v.z = hin[t] ? p0[2 * HW] : 0.f;
    v.w = hin[t] ? p0[3 * HW] : 0.f;
    hv[t] = v;
  }
}
__device__ __forceinline__ void store6(float* buf, int px, int chbase,
                                       const float4* hv) {
#pragma unroll
  for (int t = 0; t < 6; t++)
    *(float4*)(buf + (t * 32 + px) * SST + chbase) = hv[t];
}

__global__ __launch_bounds__(256, 2) void psla_attn(
    const float* __restrict__ Ft, float* __restrict__ out) {
  extern __shared__ float sm[];
  constexpr int kdx[NK] = {0, -1,-1,-1,0,0,1,1,1, -2,-2,-2,0,0,2,2,2,
                           -3,-3,-3,0,0,3,3,3, -4,-4,-4,0,0,4,4,4};
  constexpr int kdy[NK] = {0, -1,0,1,-1,1,-1,0,1, -2,0,2,-2,2,-2,0,2,
                           -3,0,3,-3,3,-3,0,3, -4,0,4,-4,4,-4,0,4};

  const int b = blockIdx.z;
  const int gx0 = blockIdx.x * 8, gy0 = blockIdx.y * 4;
  const int tid = threadIdx.x;
  const int px = tid >> 3, sub = tid & 7;
  const int lx = px & 7, ly = px >> 3;  // ly 0..3
  const int gx = gx0 + lx, gy = gy0 + ly;
  const int gp = gy * WW + gx;

  const float* Gb  = g_G + (size_t)b * CCH * HW;
  const float* Ftb = Ft + (size_t)b * CCH * HW;

  // Halo mapping: sites s = t*32 + px (t = 0..5), 16-wide x 12-tall halo.
  int ha[6];
  bool hin[6];
#pragma unroll
  for (int t = 0; t < 6; t++) {
    const int s = t * 32 + px;
    const int hy = gy0 - 4 + (s >> 4);
    const int hx = gx0 - 4 + (s & 15);
    hin[t] = ((unsigned)hy < HH) && ((unsigned)hx < WW);
    ha[t] = hy * WW + hx;
  }
  const int chbase = sub * 4;
  const float* const cbase = sm + ((ly + 4) * 16 + (lx + 4)) * SST + chbase;

  unsigned long long vmask = 0ull;
#pragma unroll
  for (int k = 0; k < NK; k++)
    if ((unsigned)(gy + kdx[k]) < HH && (unsigned)(gx + kdy[k]) < WW)
      vmask |= (1ull << k);

  float aff[NK];
#pragma unroll
  for (int k = 0; k < NK; k++) aff[k] = 0.f;

  float4 h[2][6];
  float e[3][4];

  // ==== Phase A: aff[k] = <G(p), Ft(p+delta_k)> ====
  fetch6(Ftb, 0, chbase, hin, ha, h[0]);
#pragma unroll
  for (int cc = 0; cc < 4; cc++) e[0][cc] = Gb[(size_t)(chbase + cc) * HW + gp];
  fetch6(Ftb, 32, chbase, hin, ha, h[1]);
#pragma unroll
  for (int cc = 0; cc < 4; cc++)
    e[1][cc] = Gb[(size_t)(32 + chbase + cc) * HW + gp];
  store6(sm, px, chbase, h[0]);  // buf 0 <- chunk 0
  __syncthreads();

#pragma unroll
  for (int c0 = 0; c0 < 8; c0++) {
    if (c0 < 6) {
      const int base = (c0 + 2) * 32;
      fetch6(Ftb, base, chbase, hin, ha, h[c0 & 1]);
#pragma unroll
      for (int cc = 0; cc < 4; cc++)
        e[(c0 + 2) % 3][cc] = Gb[(size_t)(base + chbase + cc) * HW + gp];
    }
    const float* bp = cbase + (c0 % 3) * ABUF;
    const float e0 = e[c0 % 3][0], e1 = e[c0 % 3][1];
    const float e2 = e[c0 % 3][2], e3 = e[c0 % 3][3];
#pragma unroll
    for (int k = 0; k < NK; k++) {
      const float4 v = *(const float4*)(bp + (kdx[k] * 16 + kdy[k]) * SST);
      float s = fmaf(e0, v.x, 0.f);
      s = fmaf(e1, v.y, s);
      s = fmaf(e2, v.z, s);
      s = fmaf(e3, v.w, s);
      aff[k] += s;
    }
    if (c0 < 7)
      store6(sm + ((c0 + 1) % 3) * ABUF, px, chbase, h[(c0 + 1) & 1]);
    __syncthreads();
  }

  // Reduce partial dots across the 8 channel-subgroups (lanes xor 1,2,4).
#pragma unroll
  for (int k = 0; k < NK; k++) {
    aff[k] += __shfl_xor_sync(0xffffffffu, aff[k], 1);
    aff[k] += __shfl_xor_sync(0xffffffffu, aff[k], 2);
    aff[k] += __shfl_xor_sync(0xffffffffu, aff[k], 4);
  }

  // ==== Softmax over valid offsets (k=0 always valid) ====
  float m = aff[0];
#pragma unroll
  for (int k = 1; k < NK; k++)
    if ((vmask >> k) & 1ull) m = fmaxf(m, aff[k]);
  float ssum = 0.f;
#pragma unroll
  for (int k = 0; k < NK; k++) {
    if ((vmask >> k) & 1ull) {
      aff[k] = __expf(aff[k] - m);
      ssum += aff[k];
    } else {
      aff[k] = 0.f;
    }
  }
  const float inv = 1.f / ssum;
#pragma unroll
  for (int k = 0; k < NK; k++) aff[k] *= inv;

  // ==== Phase B: out(c,p) = sum_k w_k * Ft(c, p + delta_k), FFMA2 ====
  fetch6(Ftb, 0, chbase, hin, ha, h[0]);
  fetch6(Ftb, 32, chbase, hin, ha, h[1]);
  store6(sm, px, chbase, h[0]);
  __syncthreads();

#pragma unroll
  for (int c0 = 0; c0 < 8; c0++) {
    if (c0 < 6)
      fetch6(Ftb, (c0 + 2) * 32, chbase, hin, ha, h[c0 & 1]);

    const float* bp = cbase + (c0 % 3) * ABUF;
    unsigned long long a01 = 0ull, a23 = 0ull;
#pragma unroll
    for (int k = 0; k < NK; k++) {
      const ulonglong2 vv =
          *(const ulonglong2*)(bp + (kdx[k] * 16 + kdy[k]) * SST);
      const unsigned long long wk2 = pack2_bcast(aff[k]);
      a01 = ffma2(wk2, vv.x, a01);
      a23 = ffma2(wk2, vv.y, a23);
    }
    float o0, o1, o2, o3;
    unpack2(a01, o0, o1);
    unpack2(a23, o2, o3);
    float* op = out + (size_t)(b * CCH + c0 * 32 + chbase) * HW + gp;
    op[0] = o0;
    op[HW] = o1;
    op[2 * HW] = o2;
    op[3 * HW] = o3;

    if (c0 < 7)
      store6(sm + ((c0 + 1) % 3) * ABUF, px, chbase, h[(c0 + 1) & 1]);
    __syncthreads();
  }
}

// ---------------------------------------------------------------------------
extern "C" void kernel_launch(void* const* d_in, const int* in_sizes, int n_in,
                              void* d_out, int out_size) {
  const float* Ft  = (const float*)d_in[0];
  const float* Fte = (const float*)d_in[1];
  const float* Wf  = (const float*)d_in[2];
  // d_in[3] = bf: cancels in the softmax (constant in k) — unused.
  const float* Wg  = (const float*)d_in[4];
  const float* bg  = (const float*)d_in[5];
  float* out = (float*)d_out;

  cudaFuncSetAttribute(psla_gemm_fused,
                       cudaFuncAttributeMaxDynamicSharedMemorySize, FUSED_SMEM);
  const int attn_smem = 3 * ABUF * (int)sizeof(float);  // 82944 B
  cudaFuncSetAttribute(psla_attn, cudaFuncAttributeMaxDynamicSharedMemorySize,
                       attn_smem);

  psla_gemm_fused<<<128, 256, FUSED_SMEM>>>(Fte, Wf, Wg, bg);

  dim3 ga(8, 16, 2);  // W/8, H/4, B
  psla_attn<<<ga, 256, attn_smem>>>(Ft, out);
}

// round 15
// speedup vs baseline: 1.3228x; 1.3228x over previous
#include <cuda_runtime.h>
#include <cstdint>

#define HH 64
#define WW 64
#define HW 4096
#define CCH 256
#define NK 33

// Scratch
__device__ float g_G[2u * 256u * 4096u];  // G[b][d][p] = Mt @ Fte + u
__device__ float g_M[256u * 256u];        // Mt[d][c]
__device__ float g_u[256u];               // u[d]
__device__ unsigned g_gate = 0u;
__device__ unsigned g_done = 0u;

// ---------------------------------------------------------------------------
// f32x2 packed helpers (FFMA2 via PTX fma.rn.f32x2)
// ---------------------------------------------------------------------------
__device__ __forceinline__ unsigned long long pack2_bcast(float x) {
  unsigned long long r;
  asm("mov.b64 %0, {%1, %1};" : "=l"(r) : "f"(x));
  return r;
}
__device__ __forceinline__ unsigned long long ffma2(unsigned long long a,
                                                    unsigned long long b,
                                                    unsigned long long c) {
  unsigned long long d;
  asm("fma.rn.f32x2 %0, %1, %2, %3;" : "=l"(d) : "l"(a), "l"(b), "l"(c));
  return d;
}
__device__ __forceinline__ void unpack2(unsigned long long v, float& lo, float& hi) {
  asm("mov.b64 {%0, %1}, %2;" : "=f"(lo), "=f"(hi) : "l"(v));
}

// ---------------------------------------------------------------------------
// Kernel 1 (fused): prep (Mt, u) + G = Mt @ Fte + u.
// v2: 256 CTAs, GEMM tile = 128 o x 64 p -> 2 CTAs/SM (cross-CTA overlap).
//   CTA 0..63 : 32x32 Mt tile;  CTA 64 : u;  all: gate, then GEMM tile.
// Deadlock-safe: gate releasers (bid 0..64) are in scheduling wave 1 even
// at 1 CTA/SM occupancy.
// ---------------------------------------------------------------------------
#define PSTR 36
#define FUSED_SMEM (2 * 256 * PSTR * (int)sizeof(float))  // 73728 B

__global__ __launch_bounds__(256, 2) void psla_gemm_fused(
    const float* __restrict__ Fte, const float* __restrict__ Wf,
    const float* __restrict__ Wg, const float* __restrict__ bg) {
  extern __shared__ float dsm[];
  const int bid = blockIdx.x;
  const int tid = threadIdx.x;

  // ===== Phase 0: prep (first 65 CTAs) =====
  if (bid < 64) {
    float (*sg)[PSTR] = (float (*)[PSTR])dsm;
    float (*sf)[PSTR] = (float (*)[PSTR])(dsm + 256 * PSTR);
    const int c0 = (bid & 7) * 32;
    const int d0 = (bid >> 3) * 32;

    float4 ga[8], fa[8];
#pragma unroll
    for (int j = 0; j < 8; j++) {
      ga[j] = *(const float4*)(Wg + (size_t)tid * 256 + c0 + 4 * j);
      fa[j] = *(const float4*)(Wf + (size_t)tid * 256 + d0 + 4 * j);
    }
#pragma unroll
    for (int j = 0; j < 8; j++) {
      *(float4*)&sg[tid][4 * j] = ga[j];
      *(float4*)&sf[tid][4 * j] = fa[j];
    }
    __syncthreads();

    const int tc = (tid & 15) * 2, td = (tid >> 4) * 2;
    float a00 = 0.f, a01 = 0.f, a10 = 0.f, a11 = 0.f;
#pragma unroll 8
    for (int kk = 0; kk < 256; kk++) {
      const float2 g2 = *(const float2*)&sg[kk][tc];
      const float2 f2 = *(const float2*)&sf[kk][td];
      a00 = fmaf(f2.x, g2.x, a00);
      a01 = fmaf(f2.x, g2.y, a01);
      a10 = fmaf(f2.y, g2.x, a10);
      a11 = fmaf(f2.y, g2.y, a11);
    }
    g_M[(size_t)(d0 + td + 0) * 256 + c0 + tc + 0] = a00;
    g_M[(size_t)(d0 + td + 0) * 256 + c0 + tc + 1] = a01;
    g_M[(size_t)(d0 + td + 1) * 256 + c0 + tc + 0] = a10;
    g_M[(size_t)(d0 + td + 1) * 256 + c0 + tc + 1] = a11;

    __threadfence();
    __syncthreads();
    if (tid == 0) atomicAdd(&g_gate, 1u);
  } else if (bid == 64) {
    float s0 = 0.f, s1 = 0.f, s2 = 0.f, s3 = 0.f;
#pragma unroll
    for (int o = 0; o < 256; o += 4) {
      s0 = fmaf(bg[o + 0], Wf[(o + 0) * 256 + tid], s0);
      s1 = fmaf(bg[o + 1], Wf[(o + 1) * 256 + tid], s1);
      s2 = fmaf(bg[o + 2], Wf[(o + 2) * 256 + tid], s2);
      s3 = fmaf(bg[o + 3], Wf[(o + 3) * 256 + tid], s3);
    }
    g_u[tid] = (s0 + s1) + (s2 + s3);
    __threadfence();
    __syncthreads();
    if (tid == 0) atomicAdd(&g_gate, 1u);
  }

  // ===== Gate =====
  if (tid == 0) {
    while (atomicAdd(&g_gate, 0u) < 65u) __nanosleep(64);
  }
  __syncthreads();

  // ===== Phase 1: GEMM tile 128 o x 64 p =====
  {
    float* sA = dsm;             // [8][132]
    float* sB = dsm + 8 * 132;   // [8][68]

    const int rest = bid >> 6;           // 0..3
    const int b = rest & 1;
    const int o0 = (rest >> 1) * 128;
    const int p0 = (bid & 63) * 64;
    const float* X = Fte + (size_t)b * CCH * HW;
    float* Go = g_G + (size_t)b * CCH * HW;

    const int tx = tid & 15, ty = tid >> 4;  // 16 x 16 thread grid

    unsigned long long acc2[8][2];
#pragma unroll
    for (int i = 0; i < 8; i++) {
      acc2[i][0] = 0ull;
      acc2[i][1] = 0ull;
    }

    const int arow = tid >> 1, acg = (tid & 1) * 4;  // A: 128 rows x 8 k
    const int brow = tid >> 5, bcol = (tid & 31) * 2;  // B: 8 rows x 64 p

    for (int k0 = 0; k0 < CCH; k0 += 8) {
      float4 av = *(const float4*)(g_M + (size_t)(o0 + arow) * CCH + k0 + acg);
      float2 bv = *(const float2*)(X + (size_t)(k0 + brow) * HW + p0 + bcol);
      __syncthreads();
      sA[(acg + 0) * 132 + arow] = av.x;
      sA[(acg + 1) * 132 + arow] = av.y;
      sA[(acg + 2) * 132 + arow] = av.z;
      sA[(acg + 3) * 132 + arow] = av.w;
      *(float2*)&sB[brow * 68 + bcol] = bv;
      __syncthreads();
#pragma unroll
      for (int kk = 0; kk < 8; kk++) {
        float a[8];
        *(float4*)&a[0] = *(const float4*)&sA[kk * 132 + ty * 8];
        *(float4*)&a[4] = *(const float4*)&sA[kk * 132 + ty * 8 + 4];
        unsigned long long b2[2];
        ulonglong2 bl = *(const ulonglong2*)&sB[kk * 68 + tx * 4];
        b2[0] = bl.x;
        b2[1] = bl.y;
        unsigned long long a2[8];
#pragma unroll
        for (int i = 0; i < 8; i++) a2[i] = pack2_bcast(a[i]);
#pragma unroll
        for (int i = 0; i < 8; i++) {
          acc2[i][0] = ffma2(a2[i], b2[0], acc2[i][0]);
          acc2[i][1] = ffma2(a2[i], b2[1], acc2[i][1]);
        }
      }
    }

#pragma unroll
    for (int i = 0; i < 8; i++) {
      const int o = o0 + ty * 8 + i;
      const float bvv = g_u[o];
      float r[4];
      unpack2(acc2[i][0], r[0], r[1]);
      unpack2(acc2[i][1], r[2], r[3]);
      float4 v;
      v.x = r[0] + bvv;
      v.y = r[1] + bvv;
      v.z = r[2] + bvv;
      v.w = r[3] + bvv;
      *(float4*)(Go + (size_t)o * HW + p0 + tx * 4) = v;
    }
  }

  // ===== Reset counters for next replay (last of 256 CTAs) =====
  __syncthreads();
  if (tid == 0) {
    const unsigned d = atomicAdd(&g_done, 1u);
    if (d == 255u) {
      atomicExch(&g_gate, 0u);
      atomicExch(&g_done, 0u);
    }
  }
}

// ---------------------------------------------------------------------------
// Kernel 2: sparse local attention (R8 verbatim — proven 37.5 us).
// 8x8 pixel tile, 512 threads, triple-buffered smem halo [3][256][36].
// ---------------------------------------------------------------------------
#define SST 36
#define ABUF (256 * SST)

__device__ __forceinline__ void halo_fetch(const float* __restrict__ P,
                                           int base, int cg0, bool hin,
                                           int haddr, float4* hv) {
#pragma unroll
  for (int j = 0; j < 4; j++) {
    const int c = base + (cg0 + 2 * j) * 4;
    float4 v;
    v.x = hin ? P[(size_t)(c + 0) * HW + haddr] : 0.f;
    v.y = hin ? P[(size_t)(c + 1) * HW + haddr] : 0.f;
    v.z = hin ? P[(size_t)(c + 2) * HW + haddr] : 0.f;
    v.w = hin ? P[(size_t)(c + 3) * HW + haddr] : 0.f;
    hv[j] = v;
  }
}
__device__ __forceinline__ void halo_store(float* bufq, int cg0,
                                           const float4* hv) {
#pragma unroll
  for (int j = 0; j < 4; j++)
    *(float4*)(bufq + (cg0 + 2 * j) * 4) = hv[j];
}

__global__ __launch_bounds__(512) void psla_attn(const float* __restrict__ Ft,
                                                 float* __restrict__ out) {
  extern __shared__ float sm[];
  constexpr int kdx[NK] = {0, -1,-1,-1,0,0,1,1,1, -2,-2,-2,0,0,2,2,2,
                           -3,-3,-3,0,0,3,3,3, -4,-4,-4,0,0,4,4,4};
  constexpr int kdy[NK] = {0, -1,0,1,-1,1,-1,0,1, -2,0,2,-2,2,-2,0,2,
                           -3,0,3,-3,3,-3,0,3, -4,0,4,-4,4,-4,0,4};

  const int b = blockIdx.z;
  const int gx0 = blockIdx.x * 8, gy0 = blockIdx.y * 8;
  const int tid = threadIdx.x;
  const int px = tid >> 3, sub = tid & 7;
  const int lx = px & 7, ly = px >> 3;
  const int gx = gx0 + lx, gy = gy0 + ly;
  const int gp = gy * WW + gx;

  const float* Gb  = g_G + (size_t)b * CCH * HW;
  const float* Ftb = Ft + (size_t)b * CCH * HW;

  const int q   = tid & 255;
  const int cg0 = tid >> 8;  // 0 or 1
  const int hy = gy0 - 4 + (q >> 4);
  const int hx = gx0 - 4 + (q & 15);
  const bool hin = ((unsigned)hy < HH) && ((unsigned)hx < WW);
  const int haddr = hy * WW + hx;
  float* const myq0 = sm + q * SST;

  const float* const cbase = sm + ((ly + 4) * 16 + (lx + 4)) * SST + sub * 4;

  unsigned long long vmask = 0ull;
#pragma unroll
  for (int k = 0; k < NK; k++)
    if ((unsigned)(gy + kdx[k]) < HH && (unsigned)(gx + kdy[k]) < WW)
      vmask |= (1ull << k);

  float aff[NK];
#pragma unroll
  for (int k = 0; k < NK; k++) aff[k] = 0.f;

  float4 h[2][4];
  float e[3][4];

  // ==== Phase A: aff[k] = <G(p), Ft(p+delta_k)> ====
  halo_fetch(Ftb, 0, cg0, hin, haddr, h[0]);
#pragma unroll
  for (int cc = 0; cc < 4; cc++) e[0][cc] = Gb[(size_t)(sub * 4 + cc) * HW + gp];
  halo_fetch(Ftb, 32, cg0, hin, haddr, h[1]);
#pragma unroll
  for (int cc = 0; cc < 4; cc++)
    e[1][cc] = Gb[(size_t)(32 + sub * 4 + cc) * HW + gp];
  halo_store(myq0, cg0, h[0]);  // buf 0 <- chunk 0
  __syncthreads();

#pragma unroll
  for (int c0 = 0; c0 < 8; c0++) {
    if (c0 < 6) {
      const int base = (c0 + 2) * 32;
      halo_fetch(Ftb, base, cg0, hin, haddr, h[c0 & 1]);
#pragma unroll
      for (int cc = 0; cc < 4; cc++)
        e[(c0 + 2) % 3][cc] = Gb[(size_t)(base + sub * 4 + cc) * HW + gp];
    }
    const float* bp = cbase + (c0 % 3) * ABUF;
    const float e0 = e[c0 % 3][0], e1 = e[c0 % 3][1];
    const float e2 = e[c0 % 3][2], e3 = e[c0 % 3][3];
#pragma unroll
    for (int k = 0; k < NK; k++) {
      const float4 v = *(const float4*)(bp + (kdx[k] * 16 + kdy[k]) * SST);
      float s = fmaf(e0, v.x, 0.f);
      s = fmaf(e1, v.y, s);
      s = fmaf(e2, v.z, s);
      s = fmaf(e3, v.w, s);
      aff[k] += s;
    }
    if (c0 < 7)
      halo_store(myq0 + ((c0 + 1) % 3) * ABUF, cg0, h[(c0 + 1) & 1]);
    __syncthreads();
  }

  // Reduce partial dots across the 8 channel-subgroups (lanes xor 1,2,4).
#pragma unroll
  for (int k = 0; k < NK; k++) {
    aff[k] += __shfl_xor_sync(0xffffffffu, aff[k], 1);
    aff[k] += __shfl_xor_sync(0xffffffffu, aff[k], 2);
    aff[k] += __shfl_xor_sync(0xffffffffu, aff[k], 4);
  }

  // ==== Softmax over valid offsets (k=0 always valid) ====
  float m = aff[0];
#pragma unroll
  for (int k = 1; k < NK; k++)
    if ((vmask >> k) & 1ull) m = fmaxf(m, aff[k]);
  float ssum = 0.f;
#pragma unroll
  for (int k = 0; k < NK; k++) {
    if ((vmask >> k) & 1ull) {
      aff[k] = __expf(aff[k] - m);
      ssum += aff[k];
    } else {
      aff[k] = 0.f;
    }
  }
  const float inv = 1.f / ssum;
#pragma unroll
  for (int k = 0; k < NK; k++) aff[k] *= inv;

  // ==== Phase B: out(c,p) = sum_k w_k * Ft(c, p + delta_k), FFMA2 ====
  halo_fetch(Ftb, 0, cg0, hin, haddr, h[0]);
  halo_fetch(Ftb, 32, cg0, hin, haddr, h[1]);
  halo_store(myq0, cg0, h[0]);
  __syncthreads();

#pragma unroll
  for (int c0 = 0; c0 < 8; c0++) {
    if (c0 < 6)
      halo_fetch(Ftb, (c0 + 2) * 32, cg0, hin, haddr, h[c0 & 1]);

    const float* bp = cbase + (c0 % 3) * ABUF;
    unsigned long long a01 = 0ull, a23 = 0ull;
#pragma unroll
    for (int k = 0; k < NK; k++) {
      const ulonglong2 vv =
          *(const ulonglong2*)(bp + (kdx[k] * 16 + kdy[k]) * SST);
      const unsigned long long wk2 = pack2_bcast(aff[k]);
      a01 = ffma2(wk2, vv.x, a01);
      a23 = ffma2(wk2, vv.y, a23);
    }
    float o0, o1, o2, o3;
    unpack2(a01, o0, o1);
    unpack2(a23, o2, o3);
    float* op = out + (size_t)(b * CCH + c0 * 32 + sub * 4) * HW + gp;
    op[0] = o0;
    op[HW] = o1;
    op[2 * HW] = o2;
    op[3 * HW] = o3;

    if (c0 < 7)
      halo_store(myq0 + ((c0 + 1) % 3) * ABUF, cg0, h[(c0 + 1) & 1]);
    __syncthreads();
  }
}

// ---------------------------------------------------------------------------
extern "C" void kernel_launch(void* const* d_in, const int* in_sizes, int n_in,
                              void* d_out, int out_size) {
  const float* Ft  = (const float*)d_in[0];
  const float* Fte = (const float*)d_in[1];
  const float* Wf  = (const float*)d_in[2];
  // d_in[3] = bf: cancels in the softmax (constant in k) — unused.
  const float* Wg  = (const float*)d_in[4];
  const float* bg  = (const float*)d_in[5];
  float* out = (float*)d_out;

  cudaFuncSetAttribute(psla_gemm_fused,
                       cudaFuncAttributeMaxDynamicSharedMemorySize, FUSED_SMEM);
  const int attn_smem = 3 * ABUF * (int)sizeof(float);  // 110592 B
  cudaFuncSetAttribute(psla_attn, cudaFuncAttributeMaxDynamicSharedMemorySize,
                       attn_smem);

  psla_gemm_fused<<<256, 256, FUSED_SMEM>>>(Fte, Wf, Wg, bg);

  dim3 ga(8, 8, 2);  // W/8, H/8, B
  psla_attn<<<ga, 512, attn_smem>>>(Ft, out);
}